// round 11
// baseline (speedup 1.0000x reference)
#include <cuda_runtime.h>
#include <math.h>
#include <stdint.h>

#define NB    8
#define CC_   192
#define HH    112
#define WW    112
#define HW    (HH * WW)         // 12544
#define BAND  8                 // pixel rows per tile
#define NBAND (HH / BAND)       // 14
#define LR    10                // local rows incl. +/-1 halo
#define CPC   4                 // channels per smem chunk
#define NCHUNK 8                // chunks per block (32 channels total)
#define NBUF  2                 // ring depth (35.84 KB total -> 5 blocks/SM)
#define SPLITS 6                // channel-split blocks per tile
#define CSPLIT (CPC * NCHUNK)   // 32 channels per block
#define NTILES (NB * NBAND)     // 112
#define CHF   (CPC * LR * WW)   // 4480 floats per buffer (17920 B)
#define INV_T 10.0f
#define TOTAL_TERMS (8.0 * 8.0 * 112.0 * 112.0)

// scratch slice layout (floats): ssq[10][112] fdE[8][112] fdS[9][112] fdSE[9][112] fdSW[9][112]
#define SSQ  0
#define FDE  1120
#define FDS  2016
#define FDSE 3024
#define FDSW 4032
#define SCR  5040               // 20160 B, 16B-aligned

__device__ __align__(16) float g_scr[NTILES * SPLITS * SCR];  // ~13.5 MB
__device__ unsigned g_tile_cnt[NTILES];
__device__ double   g_acc = 0.0;
__device__ unsigned g_cnt = 0u;

// mbarrier parity wait (acquire)
#define WAIT_PARITY(maddr, ph) do {                                            \
    uint32_t _done;                                                            \
    asm volatile("{\n\t.reg .pred p;\n\t"                                      \
        "mbarrier.try_wait.parity.acquire.cta.shared::cta.b64 p, [%1], %2;\n\t"\
        "selp.b32 %0, 1, 0, p;\n\t}"                                           \
        : "=r"(_done) : "r"(maddr), "r"(ph) : "memory");                       \
    if (!_done) {                                                              \
        asm volatile("{\n\t.reg .pred P1;\n\t"                                 \
            "WL_%=:\n\t"                                                       \
            "mbarrier.try_wait.parity.acquire.cta.shared::cta.b64 P1, [%0], %1, 0x989680;\n\t" \
            "@P1 bra.uni WD_%=;\n\t"                                           \
            "bra.uni WL_%=;\n\t"                                               \
            "WD_%=:\n\t}"                                                      \
            :: "r"(maddr), "r"(ph) : "memory");                                \
    }                                                                          \
} while (0)

__global__ __launch_bounds__(256, 5)
void dcl_kernel(const float* __restrict__ feat,
                const int*   __restrict__ labels,
                const int*   __restrict__ dirs,
                float*       __restrict__ out)
{
    __shared__ __align__(16) float s[NBUF * CHF];   // 35840 B static (no 64KB rounding)
    __shared__ __align__(8) uint64_t mbar[NBUF];
    __shared__ float warpsum[8];
    __shared__ int   s_last;

    const int band  = blockIdx.x;
    const int n     = blockIdx.y;
    const int split = blockIdx.z;
    const int tile  = n * NBAND + band;
    const int tid   = threadIdx.x;

    // pixel-warp mapping (tid < 224): 4 consecutive pixels along j
    const int ri = tid / 28;            // 0..7 for tid<224
    const int jq = (tid % 28) * 4;      // 0..108
    // halo-warp mapping (warp 7)
    const int u   = tid - 224;
    const int hjq = ((u < 28 ? u : 27)) * 4;

    float a0=0,a1=0,a2=0,a3=0;
    float e0=0,e1=0,e2=0,e3=0;
    float f0=0,f1=0,f2=0,f3=0;
    float g0=0,g1=0,g2=0,g3=0;
    float h0=0,h1=0,h2=0,h3=0;

    const float* fbase = feat + ((size_t)n * CC_ + split * CSPLIT) * HW;
    const unsigned sb0  = (unsigned)__cvta_generic_to_shared(s);
    const unsigned mb0  = (unsigned)__cvta_generic_to_shared(mbar);

    // band geometry for bulk copies (uniform per block)
    const int  r0g  = band * BAND - 1;
    const bool top0 = (r0g < 0);                    // band 0: no row -1
    const bool bot0 = (band == NBAND - 1);          // band 13: no row +8
    const int  rbeg = top0 ? 1 : 0;                 // local row where copy lands
    const int  gbeg = top0 ? 0 : r0g;               // first global row copied
    const int  rows = (top0 || bot0) ? (LR - 1) : LR;
    const unsigned tx_bytes = (unsigned)(CPC * rows * WW * 4);

    // ---- init mbarriers + zero edge halo rows (persist: TMA never writes them) ----
    if (tid == 0) {
#pragma unroll
        for (int b = 0; b < NBUF; b++)
            asm volatile("mbarrier.init.shared.b64 [%0], %1;"
                         :: "r"(mb0 + b * 8), "r"(1u) : "memory");
    }
    if (top0 || bot0) {
        const int zr = top0 ? 0 : (LR - 1);
        for (int i = tid; i < NBUF * CPC * WW; i += 256) {
            const int b = i / (CPC * WW);
            const int rem = i - b * (CPC * WW);
            const int c = rem / WW;
            const int j = rem - c * WW;
            s[b * CHF + (c * LR + zr) * WW + j] = 0.f;
        }
    }
    __syncthreads();

    // ---- bulk-async issue of one 4-channel chunk (single thread) ----
    auto issue_chunk = [&](int ch, int b) {
        asm volatile("mbarrier.arrive.expect_tx.shared.b64 _, [%0], %1;"
                     :: "r"(mb0 + b * 8), "r"(tx_bytes) : "memory");
        const float* fp = fbase + (size_t)ch * CPC * HW + (size_t)gbeg * WW;
        const unsigned dbase = sb0 + (unsigned)b * (CHF * 4);
#pragma unroll
        for (int c = 0; c < CPC; c++) {
            const float* src = fp + (size_t)c * HW;
            const unsigned dst = dbase + (unsigned)(((c * LR + rbeg) * WW) * 4);
            asm volatile(
                "cp.async.bulk.shared::cluster.global.mbarrier::complete_tx::bytes "
                "[%0], [%1], %2, [%3];"
                :: "r"(dst), "l"(src), "r"((unsigned)(rows * WW * 4)),
                   "r"(mb0 + b * 8) : "memory");
        }
    };

    // ---- prologue: 2 chunks in flight ----
    if (tid == 0) { issue_chunk(0, 0); issue_chunk(1, 1); }

    int buf = 0;
    for (int ch = 0; ch < NCHUNK; ch++) {
        const uint32_t ph = (uint32_t)((ch / NBUF) & 1);
        WAIT_PARITY(mb0 + buf * 8, ph);

        const float* sbuf = s + buf * CHF;
        if (tid < 224) {
            const float* base = sbuf + (ri + 1) * WW + jq;
            const bool hasR = (jq < 108);
            const bool hasL = (jq > 0);
#pragma unroll
            for (int c = 0; c < CPC; c++) {
                const float* rA = base + c * (LR * WW);   // pixel row
                const float* rB = rA + WW;                // row below
                const float4 x = *(const float4*)rA;
                const float xR = hasR ? rA[4]  : 0.f;
                const float4 y = *(const float4*)rB;
                const float yL = hasL ? rB[-1] : 0.f;
                const float yR = hasR ? rB[4]  : 0.f;
                a0=fmaf(x.x,x.x,a0); a1=fmaf(x.y,x.y,a1); a2=fmaf(x.z,x.z,a2); a3=fmaf(x.w,x.w,a3);
                e0=fmaf(x.x,x.y,e0); e1=fmaf(x.y,x.z,e1); e2=fmaf(x.z,x.w,e2); e3=fmaf(x.w,xR ,e3);
                f0=fmaf(x.x,y.x,f0); f1=fmaf(x.y,y.y,f1); f2=fmaf(x.z,y.z,f2); f3=fmaf(x.w,y.w,f3);
                g0=fmaf(x.x,y.y,g0); g1=fmaf(x.y,y.z,g1); g2=fmaf(x.z,y.w,g2); g3=fmaf(x.w,yR ,g3);
                h0=fmaf(x.x,yL ,h0); h1=fmaf(x.y,y.x,h1); h2=fmaf(x.z,y.y,h2); h3=fmaf(x.w,y.z,h3);
            }
        } else {
            const float* base0 = sbuf + hjq;              // local row 0 (image row band*8-1)
            const bool hasR = (hjq < 108);
            const bool hasL = (hjq > 0);
#pragma unroll
            for (int c = 0; c < CPC; c++) {
                const float* rA = base0 + c * (LR * WW);  // row -1
                const float* rB = rA + WW;                // row 0
                const float* rT = rA + 9 * WW;            // row 8
                const float4 x = *(const float4*)rA;
                const float4 y = *(const float4*)rB;
                const float yL = hasL ? rB[-1] : 0.f;
                const float yR = hasR ? rB[4]  : 0.f;
                const float4 t = *(const float4*)rT;
                a0=fmaf(x.x,x.x,a0); a1=fmaf(x.y,x.y,a1); a2=fmaf(x.z,x.z,a2); a3=fmaf(x.w,x.w,a3);
                e0=fmaf(t.x,t.x,e0); e1=fmaf(t.y,t.y,e1); e2=fmaf(t.z,t.z,e2); e3=fmaf(t.w,t.w,e3);
                f0=fmaf(x.x,y.x,f0); f1=fmaf(x.y,y.y,f1); f2=fmaf(x.z,y.z,f2); f3=fmaf(x.w,y.w,f3);
                g0=fmaf(x.x,y.y,g0); g1=fmaf(x.y,y.z,g1); g2=fmaf(x.z,y.w,g2); g3=fmaf(x.w,yR ,g3);
                h0=fmaf(x.x,yL ,h0); h1=fmaf(x.y,y.x,h1); h2=fmaf(x.z,y.y,h2); h3=fmaf(x.w,y.z,h3);
            }
        }
        __syncthreads();   // all reads of buffer `buf` done -> safe to refill
        if (tid == 0 && ch + NBUF < NCHUNK) issue_chunk(ch + NBUF, buf);
        if (++buf == NBUF) buf = 0;
    }

    // ---- publish partials (float4 STG, private slice -> no atomics) ----
    float* scr = g_scr + ((size_t)tile * SPLITS + split) * SCR;
    if (tid < 224) {
        *(float4*)&scr[SSQ  + (ri + 1) * WW + jq] = make_float4(a0,a1,a2,a3);
        *(float4*)&scr[FDE  +  ri      * WW + jq] = make_float4(e0,e1,e2,e3);
        *(float4*)&scr[FDS  + (ri + 1) * WW + jq] = make_float4(f0,f1,f2,f3);
        *(float4*)&scr[FDSE + (ri + 1) * WW + jq] = make_float4(g0,g1,g2,g3);
        *(float4*)&scr[FDSW + (ri + 1) * WW + jq] = make_float4(h0,h1,h2,h3);
    } else if (u < 28) {
        *(float4*)&scr[SSQ  + 0 * WW + hjq] = make_float4(a0,a1,a2,a3);   // row -1 ssq
        *(float4*)&scr[SSQ  + 9 * WW + hjq] = make_float4(e0,e1,e2,e3);   // row 8 ssq
        *(float4*)&scr[FDS  + 0 * WW + hjq] = make_float4(f0,f1,f2,f3);
        *(float4*)&scr[FDSE + 0 * WW + hjq] = make_float4(g0,g1,g2,g3);
        *(float4*)&scr[FDSW + 0 * WW + hjq] = make_float4(h0,h1,h2,h3);
    }

    __threadfence();
    __syncthreads();
    if (tid == 0) {
        const unsigned old = atomicAdd(&g_tile_cnt[tile], 1u);
        s_last = (old == SPLITS - 1);
        if (s_last) g_tile_cnt[tile] = 0;  // all arrived; reset for next replay
    }
    __syncthreads();
    if (!s_last) return;
    __threadfence();

    // ---- epilogue: reduce 6 slices into smem (float4) ----
    {
        const float4* tb4 = (const float4*)(g_scr + (size_t)tile * SPLITS * SCR);
        float4* s4 = (float4*)s;
        const int Q = SCR / 4;   // 1260
        for (int i = tid; i < Q; i += 256) {
            float4 v0 = tb4[i],         v1 = tb4[Q + i],     v2 = tb4[2 * Q + i];
            float4 v3 = tb4[3 * Q + i], v4 = tb4[4 * Q + i], v5 = tb4[5 * Q + i];
            float4 r;
            r.x = v0.x + v1.x + v2.x + v3.x + v4.x + v5.x;
            r.y = v0.y + v1.y + v2.y + v3.y + v4.y + v5.y;
            r.z = v0.z + v1.z + v2.z + v3.z + v4.z + v5.z;
            r.w = v0.w + v1.w + v2.w + v3.w + v4.w + v5.w;
            s4[i] = r;
        }
    }
    __syncthreads();

    float pix = 0.f;
    if (tid < 224) {
        const float* ssq = s + SSQ;
        const int i0 = band * BAND + ri;
        const int lr = ri + 1;
#pragma unroll
        for (int k = 0; k < 4; k++) {
            const int j   = jq + k;
            const float ssc  = ssq[lr * WW + j];
            const float invp = (ssc >= 1e-24f) ? rsqrtf(ssc) : 1e12f;
            float logits[8]; int maskv[8]; float esum = 0.f;
#pragma unroll
            for (int m = 0; m < 8; m++) {
                const int d0 = __ldg(&dirs[((size_t)m * 2 + 0) * HW + i0 * WW + j]);
                const int d1 = __ldg(&dirs[((size_t)m * 2 + 1) * HW + i0 * WW + j]);
                float draw;
                if ((d0 | d1) == 0) {
                    draw = ssc;                        // self dot == sumsq
                } else {
                    const bool fwd = (d0 > 0) || (d0 == 0 && d1 > 0);
                    const int plr = fwd ? lr : lr + d0;
                    const int pj  = fwd ? j  : j  + d1;
                    const int A0  = fwd ? d0 : -d0;
                    const int A1  = fwd ? d1 : -d1;    // one of (0,1)(1,0)(1,1)(1,-1)
                    const float* base =
                        (A0 == 0) ? (s + FDE - WW)     // fdE indexed by pixel row = plr-1
                      : (A1 == 0) ? (s + FDS)
                      : (A1 > 0)  ? (s + FDSE) : (s + FDSW);
                    draw = base[plr * WW + pj];
                }
                const float ssn  = ssq[(lr + d0) * WW + (j + d1)];
                const float invq = (ssn >= 1e-24f) ? rsqrtf(ssn) : 1e12f;
                const float logit = draw * invp * invq * INV_T;
                const int labm = __ldg(&labels[(size_t)m * HW + i0 * WW + j]);
                const int labg = __ldg(&labels[(size_t)n * HW + (i0 + d0) * WW + (j + d1)]);
                const int mk   = (labm == labg);
                logits[m] = logit; maskv[m] = mk;
                esum += mk ? __expf(logit) : 0.f;
            }
            const float ld = __logf(esum + 1e-6f);
#pragma unroll
            for (int m = 0; m < 8; m++)
                pix += maskv[m] ? (ld - logits[m]) : INFINITY;
        }
    }

    // ---- block reduction + grand-total protocol (proven R3-R10) ----
    float v = pix;
#pragma unroll
    for (int off = 16; off > 0; off >>= 1)
        v += __shfl_xor_sync(0xffffffffu, v, off);
    if ((tid & 31) == 0) warpsum[tid >> 5] = v;
    __syncthreads();
    if (tid == 0) {
        double bs = 0.0;
#pragma unroll
        for (int q = 0; q < 8; q++) bs += (double)warpsum[q];
        atomicAdd(&g_acc, bs);
        __threadfence();
        const unsigned done = atomicAdd(&g_cnt, 1u);
        if (done == NTILES - 1) {
            const double total = atomicAdd(&g_acc, 0.0);  // re-read: sees all adds
            out[0] = (float)(total / TOTAL_TERMS);
            g_acc = 0.0;
            g_cnt = 0u;
        }
    }
}

extern "C" void kernel_launch(void* const* d_in, const int* in_sizes, int n_in,
                              void* d_out, int out_size)
{
    const float* feat   = (const float*)d_in[0];
    const int*   labels = (const int*)  d_in[1];
    const int*   dirs   = (const int*)  d_in[2];
    float*       out    = (float*)d_out;

    dim3 grid(NBAND, NB, SPLITS);   // (14, 8, 6) = 672 blocks, single wave at 5/SM
    dcl_kernel<<<grid, 256>>>(feat, labels, dirs, out);
}

// round 12
// speedup vs baseline: 1.2063x; 1.2063x over previous
#include <cuda_runtime.h>
#include <math.h>
#include <stdint.h>

#define NB    8
#define CC_   192
#define HH    112
#define WW    112
#define HW    (HH * WW)         // 12544
#define BAND  8                 // pixel rows per tile
#define NBAND (HH / BAND)       // 14
#define LR    10                // local rows incl. +/-1 halo
#define CPC   4                 // channels per smem chunk
#define NCHUNK 8                // chunks per block (32 channels total)
#define NBUF  2                 // ring depth (35.84 KB total)
#define SPLITS 6                // channel-split blocks per tile
#define CSPLIT (CPC * NCHUNK)   // 32 channels per block
#define NTILES (NB * NBAND)     // 112
#define CHF   (CPC * LR * WW)   // 4480 floats per buffer (17920 B)
#define INV_T 10.0f
#define TOTAL_TERMS (8.0 * 8.0 * 112.0 * 112.0)

// scratch slice layout (floats): ssq[10][112] fdE[8][112] fdS[9][112] fdSE[9][112] fdSW[9][112]
#define SSQ  0
#define FDE  1120
#define FDS  2016
#define FDSE 3024
#define FDSW 4032
#define SCR  5040               // 20160 B, 16B-aligned

__device__ __align__(16) float g_scr[NTILES * SPLITS * SCR];  // ~13.5 MB
__device__ double   g_acc = 0.0;
__device__ unsigned g_cnt = 0u;

// mbarrier parity wait (acquire)
#define WAIT_PARITY(maddr, ph) do {                                            \
    uint32_t _done;                                                            \
    asm volatile("{\n\t.reg .pred p;\n\t"                                      \
        "mbarrier.try_wait.parity.acquire.cta.shared::cta.b64 p, [%1], %2;\n\t"\
        "selp.b32 %0, 1, 0, p;\n\t}"                                           \
        : "=r"(_done) : "r"(maddr), "r"(ph) : "memory");                       \
    if (!_done) {                                                              \
        asm volatile("{\n\t.reg .pred P1;\n\t"                                 \
            "WL_%=:\n\t"                                                       \
            "mbarrier.try_wait.parity.acquire.cta.shared::cta.b64 P1, [%0], %1, 0x989680;\n\t" \
            "@P1 bra.uni WD_%=;\n\t"                                           \
            "bra.uni WL_%=;\n\t"                                               \
            "WD_%=:\n\t}"                                                      \
            :: "r"(maddr), "r"(ph) : "memory");                                \
    }                                                                          \
} while (0)

// ========================= Kernel A: mainloop only =========================
__global__ __launch_bounds__(256, 6)
void dcl_main(const float* __restrict__ feat)
{
    __shared__ __align__(16) float s[NBUF * CHF];   // 35840 B
    __shared__ __align__(8) uint64_t mbar[NBUF];

    const int band  = blockIdx.x;
    const int n     = blockIdx.y;
    const int split = blockIdx.z;
    const int tile  = n * NBAND + band;
    const int tid   = threadIdx.x;

    // pixel-warp mapping (tid < 224): 4 consecutive pixels along j
    const int ri = tid / 28;            // 0..7 for tid<224
    const int jq = (tid % 28) * 4;      // 0..108
    // halo-warp mapping (warp 7)
    const int u   = tid - 224;
    const int hjq = ((u < 28 ? u : 27)) * 4;

    float a0=0,a1=0,a2=0,a3=0;
    float e0=0,e1=0,e2=0,e3=0;
    float f0=0,f1=0,f2=0,f3=0;
    float g0=0,g1=0,g2=0,g3=0;
    float h0=0,h1=0,h2=0,h3=0;

    const float* fbase = feat + ((size_t)n * CC_ + split * CSPLIT) * HW;
    const unsigned sb0  = (unsigned)__cvta_generic_to_shared(s);
    const unsigned mb0  = (unsigned)__cvta_generic_to_shared(mbar);

    // band geometry for bulk copies (uniform per block)
    const int  r0g  = band * BAND - 1;
    const bool top0 = (r0g < 0);                    // band 0: no row -1
    const bool bot0 = (band == NBAND - 1);          // band 13: no row +8
    const int  rbeg = top0 ? 1 : 0;
    const int  gbeg = top0 ? 0 : r0g;
    const int  rows = (top0 || bot0) ? (LR - 1) : LR;
    const unsigned tx_bytes = (unsigned)(CPC * rows * WW * 4);

    // ---- init mbarriers + zero edge halo rows (persist: TMA never writes them) ----
    if (tid == 0) {
#pragma unroll
        for (int b = 0; b < NBUF; b++)
            asm volatile("mbarrier.init.shared.b64 [%0], %1;"
                         :: "r"(mb0 + b * 8), "r"(1u) : "memory");
    }
    if (top0 || bot0) {
        const int zr = top0 ? 0 : (LR - 1);
        for (int i = tid; i < NBUF * CPC * WW; i += 256) {
            const int b = i / (CPC * WW);
            const int rem = i - b * (CPC * WW);
            const int c = rem / WW;
            const int j = rem - c * WW;
            s[b * CHF + (c * LR + zr) * WW + j] = 0.f;
        }
    }
    __syncthreads();

    // ---- bulk-async issue of one 4-channel chunk (single thread) ----
    auto issue_chunk = [&](int ch, int b) {
        asm volatile("mbarrier.arrive.expect_tx.shared.b64 _, [%0], %1;"
                     :: "r"(mb0 + b * 8), "r"(tx_bytes) : "memory");
        const float* fp = fbase + (size_t)ch * CPC * HW + (size_t)gbeg * WW;
        const unsigned dbase = sb0 + (unsigned)b * (CHF * 4);
#pragma unroll
        for (int c = 0; c < CPC; c++) {
            const float* src = fp + (size_t)c * HW;
            const unsigned dst = dbase + (unsigned)(((c * LR + rbeg) * WW) * 4);
            asm volatile(
                "cp.async.bulk.shared::cluster.global.mbarrier::complete_tx::bytes "
                "[%0], [%1], %2, [%3];"
                :: "r"(dst), "l"(src), "r"((unsigned)(rows * WW * 4)),
                   "r"(mb0 + b * 8) : "memory");
        }
    };

    if (tid == 0) { issue_chunk(0, 0); issue_chunk(1, 1); }

    int buf = 0;
    for (int ch = 0; ch < NCHUNK; ch++) {
        const uint32_t ph = (uint32_t)((ch / NBUF) & 1);
        WAIT_PARITY(mb0 + buf * 8, ph);

        const float* sbuf = s + buf * CHF;
        if (tid < 224) {
            const float* base = sbuf + (ri + 1) * WW + jq;
            const bool hasR = (jq < 108);
            const bool hasL = (jq > 0);
#pragma unroll
            for (int c = 0; c < CPC; c++) {
                const float* rA = base + c * (LR * WW);   // pixel row
                const float* rB = rA + WW;                // row below
                const float4 x = *(const float4*)rA;
                const float xR = hasR ? rA[4]  : 0.f;
                const float4 y = *(const float4*)rB;
                const float yL = hasL ? rB[-1] : 0.f;
                const float yR = hasR ? rB[4]  : 0.f;
                a0=fmaf(x.x,x.x,a0); a1=fmaf(x.y,x.y,a1); a2=fmaf(x.z,x.z,a2); a3=fmaf(x.w,x.w,a3);
                e0=fmaf(x.x,x.y,e0); e1=fmaf(x.y,x.z,e1); e2=fmaf(x.z,x.w,e2); e3=fmaf(x.w,xR ,e3);
                f0=fmaf(x.x,y.x,f0); f1=fmaf(x.y,y.y,f1); f2=fmaf(x.z,y.z,f2); f3=fmaf(x.w,y.w,f3);
                g0=fmaf(x.x,y.y,g0); g1=fmaf(x.y,y.z,g1); g2=fmaf(x.z,y.w,g2); g3=fmaf(x.w,yR ,g3);
                h0=fmaf(x.x,yL ,h0); h1=fmaf(x.y,y.x,h1); h2=fmaf(x.z,y.y,h2); h3=fmaf(x.w,y.z,h3);
            }
        } else {
            const float* base0 = sbuf + hjq;              // local row 0 (image row band*8-1)
            const bool hasR = (hjq < 108);
            const bool hasL = (hjq > 0);
#pragma unroll
            for (int c = 0; c < CPC; c++) {
                const float* rA = base0 + c * (LR * WW);  // row -1
                const float* rB = rA + WW;                // row 0
                const float* rT = rA + 9 * WW;            // row 8
                const float4 x = *(const float4*)rA;
                const float4 y = *(const float4*)rB;
                const float yL = hasL ? rB[-1] : 0.f;
                const float yR = hasR ? rB[4]  : 0.f;
                const float4 t = *(const float4*)rT;
                a0=fmaf(x.x,x.x,a0); a1=fmaf(x.y,x.y,a1); a2=fmaf(x.z,x.z,a2); a3=fmaf(x.w,x.w,a3);
                e0=fmaf(t.x,t.x,e0); e1=fmaf(t.y,t.y,e1); e2=fmaf(t.z,t.z,e2); e3=fmaf(t.w,t.w,e3);
                f0=fmaf(x.x,y.x,f0); f1=fmaf(x.y,y.y,f1); f2=fmaf(x.z,y.z,f2); f3=fmaf(x.w,y.w,f3);
                g0=fmaf(x.x,y.y,g0); g1=fmaf(x.y,y.z,g1); g2=fmaf(x.z,y.w,g2); g3=fmaf(x.w,yR ,g3);
                h0=fmaf(x.x,yL ,h0); h1=fmaf(x.y,y.x,h1); h2=fmaf(x.z,y.y,h2); h3=fmaf(x.w,y.z,h3);
            }
        }
        __syncthreads();   // all reads of buffer `buf` done -> safe to refill
        if (tid == 0 && ch + NBUF < NCHUNK) issue_chunk(ch + NBUF, buf);
        if (++buf == NBUF) buf = 0;
    }

    // ---- publish partials and exit (ordering provided by kernel boundary) ----
    float* scr = g_scr + ((size_t)tile * SPLITS + split) * SCR;
    if (tid < 224) {
        *(float4*)&scr[SSQ  + (ri + 1) * WW + jq] = make_float4(a0,a1,a2,a3);
        *(float4*)&scr[FDE  +  ri      * WW + jq] = make_float4(e0,e1,e2,e3);
        *(float4*)&scr[FDS  + (ri + 1) * WW + jq] = make_float4(f0,f1,f2,f3);
        *(float4*)&scr[FDSE + (ri + 1) * WW + jq] = make_float4(g0,g1,g2,g3);
        *(float4*)&scr[FDSW + (ri + 1) * WW + jq] = make_float4(h0,h1,h2,h3);
    } else if (u < 28) {
        *(float4*)&scr[SSQ  + 0 * WW + hjq] = make_float4(a0,a1,a2,a3);   // row -1 ssq
        *(float4*)&scr[SSQ  + 9 * WW + hjq] = make_float4(e0,e1,e2,e3);   // row 8 ssq
        *(float4*)&scr[FDS  + 0 * WW + hjq] = make_float4(f0,f1,f2,f3);
        *(float4*)&scr[FDSE + 0 * WW + hjq] = make_float4(g0,g1,g2,g3);
        *(float4*)&scr[FDSW + 0 * WW + hjq] = make_float4(h0,h1,h2,h3);
    }
}

// ================== Kernel B: per-tile epilogue + reduction ==================
// 112 blocks x 896 threads, one pixel per thread.
__global__ __launch_bounds__(896)
void dcl_epi(const int* __restrict__ labels,
             const int* __restrict__ dirs,
             float*     __restrict__ out)
{
    __shared__ __align__(16) float s[SCR];   // 20160 B reduced slices
    __shared__ float warpsum[28];

    const int tile = blockIdx.x;
    const int n    = tile / NBAND;
    const int band = tile - n * NBAND;
    const int tid  = threadIdx.x;

    // ---- reduce 6 slices into smem (float4) ----
    {
        const float4* tb4 = (const float4*)(g_scr + (size_t)tile * SPLITS * SCR);
        float4* s4 = (float4*)s;
        const int Q = SCR / 4;   // 1260
        for (int i = tid; i < Q; i += 896) {
            float4 v0 = tb4[i],         v1 = tb4[Q + i],     v2 = tb4[2 * Q + i];
            float4 v3 = tb4[3 * Q + i], v4 = tb4[4 * Q + i], v5 = tb4[5 * Q + i];
            float4 r;
            r.x = v0.x + v1.x + v2.x + v3.x + v4.x + v5.x;
            r.y = v0.y + v1.y + v2.y + v3.y + v4.y + v5.y;
            r.z = v0.z + v1.z + v2.z + v3.z + v4.z + v5.z;
            r.w = v0.w + v1.w + v2.w + v3.w + v4.w + v5.w;
            s4[i] = r;
        }
    }
    __syncthreads();

    // ---- per-pixel loss: thread = one pixel ----
    const int ri = tid / WW;        // 0..7
    const int j  = tid - ri * WW;   // 0..111
    const int i0 = band * BAND + ri;
    const int lr = ri + 1;

    const float* ssq = s + SSQ;
    const float ssc  = ssq[lr * WW + j];
    const float invp = (ssc >= 1e-24f) ? rsqrtf(ssc) : 1e12f;

    float logits[8]; int maskv[8]; float esum = 0.f;
#pragma unroll
    for (int m = 0; m < 8; m++) {
        const int d0 = __ldg(&dirs[((size_t)m * 2 + 0) * HW + i0 * WW + j]);
        const int d1 = __ldg(&dirs[((size_t)m * 2 + 1) * HW + i0 * WW + j]);
        float draw;
        if ((d0 | d1) == 0) {
            draw = ssc;                        // self dot == sumsq
        } else {
            const bool fwd = (d0 > 0) || (d0 == 0 && d1 > 0);
            const int plr = fwd ? lr : lr + d0;
            const int pj  = fwd ? j  : j  + d1;
            const int A0  = fwd ? d0 : -d0;
            const int A1  = fwd ? d1 : -d1;    // one of (0,1)(1,0)(1,1)(1,-1)
            const float* base =
                (A0 == 0) ? (s + FDE - WW)     // fdE indexed by pixel row = plr-1
              : (A1 == 0) ? (s + FDS)
              : (A1 > 0)  ? (s + FDSE) : (s + FDSW);
            draw = base[plr * WW + pj];
        }
        const float ssn  = ssq[(lr + d0) * WW + (j + d1)];
        const float invq = (ssn >= 1e-24f) ? rsqrtf(ssn) : 1e12f;
        const float logit = draw * invp * invq * INV_T;
        const int labm = __ldg(&labels[(size_t)m * HW + i0 * WW + j]);
        const int labg = __ldg(&labels[(size_t)n * HW + (i0 + d0) * WW + (j + d1)]);
        const int mk   = (labm == labg);
        logits[m] = logit; maskv[m] = mk;
        esum += mk ? __expf(logit) : 0.f;
    }
    const float ld = __logf(esum + 1e-6f);
    float pix = 0.f;
#pragma unroll
    for (int m = 0; m < 8; m++)
        pix += maskv[m] ? (ld - logits[m]) : INFINITY;

    // ---- block reduction + grand-total protocol (proven R3-R11) ----
    float v = pix;
#pragma unroll
    for (int off = 16; off > 0; off >>= 1)
        v += __shfl_xor_sync(0xffffffffu, v, off);
    if ((tid & 31) == 0) warpsum[tid >> 5] = v;
    __syncthreads();
    if (tid == 0) {
        double bs = 0.0;
#pragma unroll
        for (int q = 0; q < 28; q++) bs += (double)warpsum[q];
        atomicAdd(&g_acc, bs);
        __threadfence();
        const unsigned done = atomicAdd(&g_cnt, 1u);
        if (done == NTILES - 1) {
            const double total = atomicAdd(&g_acc, 0.0);  // re-read: sees all adds
            out[0] = (float)(total / TOTAL_TERMS);
            g_acc = 0.0;
            g_cnt = 0u;
        }
    }
}

extern "C" void kernel_launch(void* const* d_in, const int* in_sizes, int n_in,
                              void* d_out, int out_size)
{
    const float* feat   = (const float*)d_in[0];
    const int*   labels = (const int*)  d_in[1];
    const int*   dirs   = (const int*)  d_in[2];
    float*       out    = (float*)d_out;

    dim3 grid(NBAND, NB, SPLITS);   // (14, 8, 6) = 672 blocks
    dcl_main<<<grid, 256>>>(feat);
    dcl_epi<<<NTILES, 896>>>(labels, dirs, out);
}